// round 5
// baseline (speedup 1.0000x reference)
#include <cuda_runtime.h>
#include <cuda_bf16.h>
#include <cstdint>
#include <cstring>

// Problem constants
#define T_ROWS   8192
#define KDIM     4096
#define NI       63
#define NPAD     64
#define NLEAF    64
#define NCLS     10

// Tiling
#define BM       64
#define BK       64
#define NKT      (KDIM / BK)     // 64 k-tiles
#define THREADS  512             // 16 warps: (kh, mw, nh)
#define STAGES   6               // 6 buffers, 5 groups in flight

#define XROW_WORDS 72            // fp32 words per X smem row (288B, conflict-free LDS.64)
#define XSTG_WORDS (BM * XROW_WORDS)          // 4608 words = 18432 B
#define WSTG_BYTES (NPAD * 128)               // 8192 B (64 rows x 128B, swizzled)
#define DYN_SMEM   (STAGES * (XSTG_WORDS * 4 + WSTG_BYTES))   // 159744 B

// Scratch (allocation-free rule: __device__ globals)
__device__ __nv_bfloat16 g_Wbf[NPAD * KDIM];
__device__ float         g_leaf_r[NLEAF];

// ---------------------------------------------------------------------------
// Prep: W -> bf16 (padded to 64 rows), leaf_r, zero output scalar.
// ---------------------------------------------------------------------------
__global__ void prep_kernel(const float* __restrict__ W,
                            const float* __restrict__ leaf_dist,
                            const float* __restrict__ class_reward,
                            float* __restrict__ out) {
    int idx  = blockIdx.x * blockDim.x + threadIdx.x;
    int base = idx * 4;
    if (base < NPAD * KDIM) {
        int n = base / KDIM;
        int k = base - n * KDIM;
        float4 v = make_float4(0.f, 0.f, 0.f, 0.f);
        if (n < NI) v = *reinterpret_cast<const float4*>(W + n * KDIM + k);
        __nv_bfloat162 lo = __floats2bfloat162_rn(v.x, v.y);
        __nv_bfloat162 hi = __floats2bfloat162_rn(v.z, v.w);
        uint32_t ulo, uhi;
        memcpy(&ulo, &lo, 4);
        memcpy(&uhi, &hi, 4);
        *reinterpret_cast<uint2*>(g_Wbf + base) = make_uint2(ulo, uhi);
    }
    if (blockIdx.x == 0) {
        int t = threadIdx.x;
        if (t < NLEAF) {
            const float* ld = leaf_dist + t * NCLS;
            float mx = ld[0];
            #pragma unroll
            for (int c = 1; c < NCLS; ++c) mx = fmaxf(mx, ld[c]);
            float s = 0.f, r = 0.f;
            #pragma unroll
            for (int c = 0; c < NCLS; ++c) {
                float e = __expf(ld[c] - mx);
                s += e;
                r += e * class_reward[c];
            }
            g_leaf_r[t] = r / s;
        }
        if (t == 0) out[0] = 0.f;
    }
}

// ---------------------------------------------------------------------------
// Helpers
// ---------------------------------------------------------------------------
__device__ __forceinline__ uint32_t smem_u32(const void* p) {
    return (uint32_t)__cvta_generic_to_shared(p);
}
__device__ __forceinline__ void cp16(void* dst, const void* src) {
    uint32_t d = smem_u32(dst);
    asm volatile("cp.async.cg.shared.global [%0], [%1], 16;\n" :: "r"(d), "l"(src));
}
__device__ __forceinline__ uint32_t pack_bf16(float x, float y) {
    __nv_bfloat162 h = __floats2bfloat162_rn(x, y);
    uint32_t u;
    memcpy(&u, &h, 4);
    return u;
}

// ---------------------------------------------------------------------------
// Main: cp.async 6-stage pipeline; 16 warps, split-k-in-tile (kh), X fp32 in
// smem (A frags via LDS.64+cvt), W bf16 swizzled (ldmatrix); sigmoid + tree.
// ---------------------------------------------------------------------------
__global__ __launch_bounds__(THREADS, 1)
void sdt_main(const float* __restrict__ X,
              const float* __restrict__ b,
              const float* __restrict__ beta,
              float* __restrict__ out) {
    extern __shared__ __align__(16) unsigned char dynsm[];
    float*         Xs  = reinterpret_cast<float*>(dynsm);
    unsigned char* Wsb = dynsm + STAGES * XSTG_WORDS * 4;
    float*         Ps  = reinterpret_cast<float*>(dynsm);              // final P, stride 65
    float*         Zs  = reinterpret_cast<float*>(dynsm) + BM * (NPAD + 1);  // partial z

    __shared__ float s_b[NPAD], s_beta[NPAD];

    const int tid  = threadIdx.x;
    const int lane = tid & 31;
    const int warp = tid >> 5;      // 0..15
    const int kh   = warp >> 3;     // 0..1 : which kk half
    const int mw   = (warp >> 1) & 3;  // 0..3 : 16-row slab
    const int nh   = warp & 1;      // 0..1 : 32-col half
    const int m0   = blockIdx.x * BM;

    if (tid < NPAD) {
        s_b[tid]    = (tid < NI) ? b[tid]    : 0.f;
        s_beta[tid] = (tid < NI) ? beta[tid] : 0.f;
    }

    const float* Xg = X + (size_t)m0 * KDIM;

    // ---- stage issue: 512 threads, X: 2 x 16B, W: 1 x 16B per thread ----
    auto issue_stage = [&](int kt) {
        if (kt < NKT) {
            unsigned char* xb = reinterpret_cast<unsigned char*>(Xs + (kt % STAGES) * XSTG_WORDS);
            const float*   xs = Xg + kt * BK;
            #pragma unroll
            for (int i = 0; i < 2; ++i) {
                int c   = tid + i * 512;          // 0..1023
                int row = c >> 4;
                int gr  = c & 15;
                cp16(xb + row * (XROW_WORDS * 4) + gr * 16, xs + row * KDIM + gr * 4);
            }
            unsigned char* wb = Wsb + (kt % STAGES) * WSTG_BYTES;
            const __nv_bfloat16* ws = g_Wbf + kt * BK;
            {
                int row = tid >> 3;
                int gr  = tid & 7;
                cp16(wb + row * 128 + ((gr ^ (row & 7)) * 16), ws + row * KDIM + gr * 8);
            }
        }
        asm volatile("cp.async.commit_group;\n" ::: "memory");
    };

    // prologue: 5 stages in flight
    for (int s = 0; s < STAGES - 1; ++s) issue_stage(s);

    float acc[4][4];
    #pragma unroll
    for (int t = 0; t < 4; ++t)
        #pragma unroll
        for (int c = 0; c < 4; ++c) acc[t][c] = 0.f;

    // lane geometry
    const int aq    = lane >> 2;
    const int at2   = (lane & 3) * 2;
    const int arow  = mw * 16 + aq;
    const int brow0 = nh * 32 + ((lane & 16) >> 1) + (lane & 7);
    const int bksel = (lane & 8) >> 3;
    const int bswz  = lane & 7;

    for (int kt = 0; kt < NKT; ++kt) {
        asm volatile("cp.async.wait_group %0;\n" :: "n"(STAGES - 2) : "memory"); // stage kt ready
        __syncthreads();                                                         // oldest buffer free
        issue_stage(kt + STAGES - 1);

        const float*         xb = Xs + (kt % STAGES) * XSTG_WORDS;
        const unsigned char* wb = Wsb + (kt % STAGES) * WSTG_BYTES;

        #pragma unroll
        for (int kx = 0; kx < 2; ++kx) {
            const int kk = kh * 2 + kx;
            // A fragment: 4 x LDS.64 (fp32) + cvt to bf16x2
            const float* pr = xb + arow * XROW_WORDS + kk * 16 + at2;
            float2 v00 = *reinterpret_cast<const float2*>(pr);
            float2 v10 = *reinterpret_cast<const float2*>(pr + 8 * XROW_WORDS);
            float2 v01 = *reinterpret_cast<const float2*>(pr + 8);
            float2 v11 = *reinterpret_cast<const float2*>(pr + 8 * XROW_WORDS + 8);
            uint32_t a0 = pack_bf16(v00.x, v00.y);
            uint32_t a1 = pack_bf16(v10.x, v10.y);
            uint32_t a2 = pack_bf16(v01.x, v01.y);
            uint32_t a3 = pack_bf16(v11.x, v11.y);

            // B fragments: 2 x ldmatrix.x4 from swizzled bf16 W
            uint32_t bb[2][4];
            #pragma unroll
            for (int g = 0; g < 2; ++g) {
                int      row   = brow0 + g * 16;
                uint32_t baddr = smem_u32(wb + row * 128 + (((kk * 2 + bksel) ^ bswz) * 16));
                asm volatile("ldmatrix.sync.aligned.m8n8.x4.shared.b16 {%0,%1,%2,%3}, [%4];\n"
                             : "=r"(bb[g][0]), "=r"(bb[g][1]), "=r"(bb[g][2]), "=r"(bb[g][3])
                             : "r"(baddr));
            }
            #pragma unroll
            for (int t = 0; t < 4; ++t) {
                const int g = t >> 1, p = (t & 1) * 2;
                asm volatile(
                    "mma.sync.aligned.m16n8k16.row.col.f32.bf16.bf16.f32 "
                    "{%0,%1,%2,%3}, {%4,%5,%6,%7}, {%8,%9}, {%0,%1,%2,%3};\n"
                    : "+f"(acc[t][0]), "+f"(acc[t][1]), "+f"(acc[t][2]), "+f"(acc[t][3])
                    : "r"(a0), "r"(a1), "r"(a2), "r"(a3), "r"(bb[g][p]), "r"(bb[g][p + 1]));
            }
        }
    }

    // drain, then all warps done with GEMM smem
    asm volatile("cp.async.wait_group 0;\n" ::: "memory");
    __syncthreads();

    // --- combine kh halves + sigmoid ---
    // kh=0 warps write partial accumulators to Zs
    if (kh == 0) {
        #pragma unroll
        for (int t = 0; t < 4; ++t) {
            const int ncol = nh * 32 + t * 8 + (lane & 3) * 2;
            const int row  = mw * 16 + (lane >> 2);
            #pragma unroll
            for (int h = 0; h < 2; ++h) {
                const int r = row + h * 8;
                #pragma unroll
                for (int j = 0; j < 2; ++j)
                    Zs[r * (NPAD + 1) + ncol + j] = acc[t][h * 2 + j];
            }
        }
    }
    __syncthreads();
    // kh=1 warps add their half, apply bias/beta/sigmoid, store P
    if (kh == 1) {
        #pragma unroll
        for (int t = 0; t < 4; ++t) {
            const int ncol = nh * 32 + t * 8 + (lane & 3) * 2;
            const int row  = mw * 16 + (lane >> 2);
            #pragma unroll
            for (int h = 0; h < 2; ++h) {
                const int r = row + h * 8;
                #pragma unroll
                for (int j = 0; j < 2; ++j) {
                    const int n = ncol + j;
                    if (n < NI) {
                        float z = acc[t][h * 2 + j] + Zs[r * (NPAD + 1) + n] + s_b[n];
                        float u = s_beta[n] * z;
                        float P = 1.f / (1.f + __expf(-u));
                        Ps[r * (NPAD + 1) + n] = P;
                    }
                }
            }
        }
    }
    __syncthreads();

    // --- tree walk: 16 warps x 4 rows; lane handles leaves (lane, lane+32) ---
    const float lr0 = g_leaf_r[lane];
    const float lr1 = g_leaf_r[lane + 32];
    float wsum = 0.f;
    #pragma unroll
    for (int r = 0; r < 4; ++r) {
        const int row = warp * 4 + r;
        const float* Pr = Ps + row * (NPAD + 1);
        float v0 = 1.f, v1 = 1.f;
        const int L0 = lane, L1 = lane + 32;
        #pragma unroll
        for (int k = 0; k < 6; ++k) {
            const int off = (1 << k) - 1;
            const float P0 = Pr[off + (L0 >> (6 - k))];
            const float P1 = Pr[off + (L1 >> (6 - k))];
            v0 *= ((L0 >> (5 - k)) & 1) ? (1.f - P0) : P0;
            v1 *= ((L1 >> (5 - k)) & 1) ? (1.f - P1) : P1;
        }
        wsum += v0 * lr0 + v1 * lr1;
    }
    #pragma unroll
    for (int s = 16; s > 0; s >>= 1)
        wsum += __shfl_down_sync(0xffffffffu, wsum, s);
    if (lane == 0) atomicAdd(out, wsum);
}

// ---------------------------------------------------------------------------
// kernel_launch
// ---------------------------------------------------------------------------
extern "C" void kernel_launch(void* const* d_in, const int* in_sizes, int n_in,
                              void* d_out, int out_size) {
    const float* X    = (const float*)d_in[0];
    const float* W    = (const float*)d_in[1];
    const float* b    = (const float*)d_in[2];
    const float* beta = (const float*)d_in[3];
    const float* leaf = (const float*)d_in[4];
    const float* cls  = (const float*)d_in[5];
    float* out = (float*)d_out;

    cudaFuncSetAttribute(sdt_main, cudaFuncAttributeMaxDynamicSharedMemorySize, DYN_SMEM);

    prep_kernel<<<256, 256>>>(W, leaf, cls, out);
    sdt_main<<<T_ROWS / BM, THREADS, DYN_SMEM>>>(X, b, beta, out);
}

// round 6
// speedup vs baseline: 1.1541x; 1.1541x over previous
#include <cuda_runtime.h>
#include <cuda_bf16.h>
#include <cstdint>
#include <cstring>

// Problem constants
#define T_ROWS   8192
#define KDIM     4096
#define NI       63
#define NPAD     64
#define NLEAF    64
#define NCLS     10

// Tiling
#define BM       32
#define BK       64
#define NKT      (KDIM / BK)     // 64 k-tiles
#define THREADS  256             // 8 warps: (kh, mw, nh)
#define STAGES   5               // 5 buffers, 4 groups in flight

#define XROW_WORDS 72            // fp32 words per X smem row (288B, conflict-free LDS.64)
#define XSTG_WORDS (BM * XROW_WORDS)          // 2304 words = 9216 B
#define WSTG_BYTES (NPAD * 128)               // 8192 B (64 rows x 128B, swizzled)
#define DYN_SMEM   (STAGES * (XSTG_WORDS * 4 + WSTG_BYTES))   // 87040 B -> 2 CTAs/SM

// Scratch (allocation-free rule: __device__ globals)
__device__ __nv_bfloat16 g_Wbf[NPAD * KDIM];
__device__ float         g_leaf_r[NLEAF];

// ---------------------------------------------------------------------------
// Prep: W -> bf16 (padded to 64 rows), leaf_r, zero output scalar.
// ---------------------------------------------------------------------------
__global__ void prep_kernel(const float* __restrict__ W,
                            const float* __restrict__ leaf_dist,
                            const float* __restrict__ class_reward,
                            float* __restrict__ out) {
    int idx  = blockIdx.x * blockDim.x + threadIdx.x;
    int base = idx * 4;
    if (base < NPAD * KDIM) {
        int n = base / KDIM;
        int k = base - n * KDIM;
        float4 v = make_float4(0.f, 0.f, 0.f, 0.f);
        if (n < NI) v = *reinterpret_cast<const float4*>(W + n * KDIM + k);
        __nv_bfloat162 lo = __floats2bfloat162_rn(v.x, v.y);
        __nv_bfloat162 hi = __floats2bfloat162_rn(v.z, v.w);
        uint32_t ulo, uhi;
        memcpy(&ulo, &lo, 4);
        memcpy(&uhi, &hi, 4);
        *reinterpret_cast<uint2*>(g_Wbf + base) = make_uint2(ulo, uhi);
    }
    if (blockIdx.x == 0) {
        int t = threadIdx.x;
        if (t < NLEAF) {
            const float* ld = leaf_dist + t * NCLS;
            float mx = ld[0];
            #pragma unroll
            for (int c = 1; c < NCLS; ++c) mx = fmaxf(mx, ld[c]);
            float s = 0.f, r = 0.f;
            #pragma unroll
            for (int c = 0; c < NCLS; ++c) {
                float e = __expf(ld[c] - mx);
                s += e;
                r += e * class_reward[c];
            }
            g_leaf_r[t] = r / s;
        }
        if (t == 0) out[0] = 0.f;
    }
}

// ---------------------------------------------------------------------------
// Helpers
// ---------------------------------------------------------------------------
__device__ __forceinline__ uint32_t smem_u32(const void* p) {
    return (uint32_t)__cvta_generic_to_shared(p);
}
__device__ __forceinline__ void cp16(void* dst, const void* src) {
    uint32_t d = smem_u32(dst);
    asm volatile("cp.async.cg.shared.global [%0], [%1], 16;\n" :: "r"(d), "l"(src));
}
__device__ __forceinline__ uint32_t pack_bf16(float x, float y) {
    __nv_bfloat162 h = __floats2bfloat162_rn(x, y);
    uint32_t u;
    memcpy(&u, &h, 4);
    return u;
}

// ---------------------------------------------------------------------------
// Main: BM=32, 256 threads, 2 CTAs/SM. cp.async 5-stage pipeline; split-k-in-
// tile (kh); X fp32 in smem (LDS.64+cvt A frags), W bf16 swizzled (ldmatrix).
// ---------------------------------------------------------------------------
__global__ __launch_bounds__(THREADS, 2)
void sdt_main(const float* __restrict__ X,
              const float* __restrict__ b,
              const float* __restrict__ beta,
              float* __restrict__ out) {
    extern __shared__ __align__(16) unsigned char dynsm[];
    float*         Xs  = reinterpret_cast<float*>(dynsm);
    unsigned char* Wsb = dynsm + STAGES * XSTG_WORDS * 4;
    float*         Ps  = reinterpret_cast<float*>(dynsm);                    // final P, stride 65
    float*         Zs  = reinterpret_cast<float*>(dynsm) + BM * (NPAD + 1);  // partial z

    __shared__ float s_b[NPAD], s_beta[NPAD];

    const int tid  = threadIdx.x;
    const int lane = tid & 31;
    const int warp = tid >> 5;         // 0..7
    const int kh   = warp >> 2;        // 0..1 : kk half
    const int mw   = (warp >> 1) & 1;  // 0..1 : 16-row slab
    const int nh   = warp & 1;         // 0..1 : 32-col half
    const int m0   = blockIdx.x * BM;

    if (tid < NPAD) {
        s_b[tid]    = (tid < NI) ? b[tid]    : 0.f;
        s_beta[tid] = (tid < NI) ? beta[tid] : 0.f;
    }

    const float* Xg = X + (size_t)m0 * KDIM;

    // ---- stage issue: 256 threads, X: 2 x 16B, W: 2 x 16B per thread ----
    auto issue_stage = [&](int kt) {
        if (kt < NKT) {
            unsigned char* xb = reinterpret_cast<unsigned char*>(Xs + (kt % STAGES) * XSTG_WORDS);
            const float*   xs = Xg + kt * BK;
            #pragma unroll
            for (int i = 0; i < 2; ++i) {
                int c   = tid + i * 256;          // 0..511
                int row = c >> 4;                 // 0..31
                int gr  = c & 15;
                cp16(xb + row * (XROW_WORDS * 4) + gr * 16, xs + row * KDIM + gr * 4);
            }
            unsigned char* wb = Wsb + (kt % STAGES) * WSTG_BYTES;
            const __nv_bfloat16* ws = g_Wbf + kt * BK;
            #pragma unroll
            for (int i = 0; i < 2; ++i) {
                int c   = tid + i * 256;          // 0..511
                int row = c >> 3;                 // 0..63
                int gr  = c & 7;
                cp16(wb + row * 128 + ((gr ^ (row & 7)) * 16), ws + row * KDIM + gr * 8);
            }
        }
        asm volatile("cp.async.commit_group;\n" ::: "memory");
    };

    // prologue: 4 stages in flight
    for (int s = 0; s < STAGES - 1; ++s) issue_stage(s);

    float acc[4][4];
    #pragma unroll
    for (int t = 0; t < 4; ++t)
        #pragma unroll
        for (int c = 0; c < 4; ++c) acc[t][c] = 0.f;

    // lane geometry
    const int aq    = lane >> 2;
    const int at2   = (lane & 3) * 2;
    const int arow  = mw * 16 + aq;
    const int brow0 = nh * 32 + ((lane & 16) >> 1) + (lane & 7);
    const int bksel = (lane & 8) >> 3;
    const int bswz  = lane & 7;

    for (int kt = 0; kt < NKT; ++kt) {
        asm volatile("cp.async.wait_group %0;\n" :: "n"(STAGES - 2) : "memory"); // stage kt ready
        __syncthreads();                                                         // oldest buffer free
        issue_stage(kt + STAGES - 1);

        const float*         xb = Xs + (kt % STAGES) * XSTG_WORDS;
        const unsigned char* wb = Wsb + (kt % STAGES) * WSTG_BYTES;

        #pragma unroll
        for (int kx = 0; kx < 2; ++kx) {
            const int kk = kh * 2 + kx;
            // A fragment: 4 x LDS.64 (fp32) + cvt to bf16x2
            const float* pr = xb + arow * XROW_WORDS + kk * 16 + at2;
            float2 v00 = *reinterpret_cast<const float2*>(pr);
            float2 v10 = *reinterpret_cast<const float2*>(pr + 8 * XROW_WORDS);
            float2 v01 = *reinterpret_cast<const float2*>(pr + 8);
            float2 v11 = *reinterpret_cast<const float2*>(pr + 8 * XROW_WORDS + 8);
            uint32_t a0 = pack_bf16(v00.x, v00.y);
            uint32_t a1 = pack_bf16(v10.x, v10.y);
            uint32_t a2 = pack_bf16(v01.x, v01.y);
            uint32_t a3 = pack_bf16(v11.x, v11.y);

            // B fragments: 2 x ldmatrix.x4 from swizzled bf16 W
            uint32_t bb[2][4];
            #pragma unroll
            for (int g = 0; g < 2; ++g) {
                int      row   = brow0 + g * 16;
                uint32_t baddr = smem_u32(wb + row * 128 + (((kk * 2 + bksel) ^ bswz) * 16));
                asm volatile("ldmatrix.sync.aligned.m8n8.x4.shared.b16 {%0,%1,%2,%3}, [%4];\n"
                             : "=r"(bb[g][0]), "=r"(bb[g][1]), "=r"(bb[g][2]), "=r"(bb[g][3])
                             : "r"(baddr));
            }
            #pragma unroll
            for (int t = 0; t < 4; ++t) {
                const int g = t >> 1, p = (t & 1) * 2;
                asm volatile(
                    "mma.sync.aligned.m16n8k16.row.col.f32.bf16.bf16.f32 "
                    "{%0,%1,%2,%3}, {%4,%5,%6,%7}, {%8,%9}, {%0,%1,%2,%3};\n"
                    : "+f"(acc[t][0]), "+f"(acc[t][1]), "+f"(acc[t][2]), "+f"(acc[t][3])
                    : "r"(a0), "r"(a1), "r"(a2), "r"(a3), "r"(bb[g][p]), "r"(bb[g][p + 1]));
            }
        }
    }

    // drain, then all warps done with GEMM smem
    asm volatile("cp.async.wait_group 0;\n" ::: "memory");
    __syncthreads();

    // --- combine kh halves + sigmoid ---
    if (kh == 0) {
        #pragma unroll
        for (int t = 0; t < 4; ++t) {
            const int ncol = nh * 32 + t * 8 + (lane & 3) * 2;
            const int row  = mw * 16 + (lane >> 2);
            #pragma unroll
            for (int h = 0; h < 2; ++h) {
                const int r = row + h * 8;
                #pragma unroll
                for (int j = 0; j < 2; ++j)
                    Zs[r * (NPAD + 1) + ncol + j] = acc[t][h * 2 + j];
            }
        }
    }
    __syncthreads();
    if (kh == 1) {
        #pragma unroll
        for (int t = 0; t < 4; ++t) {
            const int ncol = nh * 32 + t * 8 + (lane & 3) * 2;
            const int row  = mw * 16 + (lane >> 2);
            #pragma unroll
            for (int h = 0; h < 2; ++h) {
                const int r = row + h * 8;
                #pragma unroll
                for (int j = 0; j < 2; ++j) {
                    const int n = ncol + j;
                    if (n < NI) {
                        float z = acc[t][h * 2 + j] + Zs[r * (NPAD + 1) + n] + s_b[n];
                        float u = s_beta[n] * z;
                        float P = 1.f / (1.f + __expf(-u));
                        Ps[r * (NPAD + 1) + n] = P;
                    }
                }
            }
        }
    }
    __syncthreads();

    // --- tree walk: 8 warps x 4 rows; lane handles leaves (lane, lane+32) ---
    const float lr0 = g_leaf_r[lane];
    const float lr1 = g_leaf_r[lane + 32];
    float wsum = 0.f;
    #pragma unroll
    for (int r = 0; r < 4; ++r) {
        const int row = warp * 4 + r;
        const float* Pr = Ps + row * (NPAD + 1);
        float v0 = 1.f, v1 = 1.f;
        const int L0 = lane, L1 = lane + 32;
        #pragma unroll
        for (int k = 0; k < 6; ++k) {
            const int off = (1 << k) - 1;
            const float P0 = Pr[off + (L0 >> (6 - k))];
            const float P1 = Pr[off + (L1 >> (6 - k))];
            v0 *= ((L0 >> (5 - k)) & 1) ? (1.f - P0) : P0;
            v1 *= ((L1 >> (5 - k)) & 1) ? (1.f - P1) : P1;
        }
        wsum += v0 * lr0 + v1 * lr1;
    }
    #pragma unroll
    for (int s = 16; s > 0; s >>= 1)
        wsum += __shfl_down_sync(0xffffffffu, wsum, s);
    if (lane == 0) atomicAdd(out, wsum);
}

// ---------------------------------------------------------------------------
// kernel_launch
// ---------------------------------------------------------------------------
extern "C" void kernel_launch(void* const* d_in, const int* in_sizes, int n_in,
                              void* d_out, int out_size) {
    const float* X    = (const float*)d_in[0];
    const float* W    = (const float*)d_in[1];
    const float* b    = (const float*)d_in[2];
    const float* beta = (const float*)d_in[3];
    const float* leaf = (const float*)d_in[4];
    const float* cls  = (const float*)d_in[5];
    float* out = (float*)d_out;

    cudaFuncSetAttribute(sdt_main, cudaFuncAttributeMaxDynamicSharedMemorySize, DYN_SMEM);

    prep_kernel<<<256, 256>>>(W, leaf, cls, out);
    sdt_main<<<T_ROWS / BM, THREADS, DYN_SMEM>>>(X, b, beta, out);
}